// round 16
// baseline (speedup 1.0000x reference)
#include <cuda_runtime.h>

typedef unsigned long long ull;

#define Hh    64
#define Gg    192
#define Tt    512
#define Bb    4096
#define BT    32      // batch per CTA
#define NCTA  128
#define NTHR  512     // 16 warps; 4 groups of 128 (each group: 1 warp per SMSP)
#define PAD_H 36      // h row stride (floats)
#define SCRP  7       // scratch row stride in ull (odd*14 banks -> CF LDS.64)

struct __align__(16) Smem {
    float Wt0 [Hh][Gg];      // Whh0^T (k-major)
    float Wt1i[Hh][Gg];      // Wih1^T
    float Wt1h[Hh][Gg];      // Whh1^T
    float h0[2][Hh][PAD_H];  // double-buffered layer-0 state [buf][k][b]
    float h1[2][Hh][PAD_H];  // double-buffered layer-1 state
    float xbuf[2][BT][2];    // double-buffered x_t
    ull   scr[4][2][Hh][SCRP]; // partial-sum exchange [group][srcHalf][j][6 used]
};

__device__ __forceinline__ ull dup2(float a) {
    ull r; asm("mov.b64 %0, {%1, %1};" : "=l"(r) : "f"(a)); return r;
}
__device__ __forceinline__ void upk2(ull v, float& lo, float& hi) {
    asm("mov.b64 {%0, %1}, %2;" : "=f"(lo), "=f"(hi) : "l"(v));
}
__device__ __forceinline__ void fma2(ull& d, ull a, ull b) {
    asm("fma.rn.f32x2 %0, %1, %2, %0;" : "+l"(d) : "l"(a), "l"(b));
}
__device__ __forceinline__ ull fadd2(ull a, ull b) {
    ull r; asm("add.rn.f32x2 %0, %1, %2;" : "=l"(r) : "l"(a), "l"(b)); return r;
}
__device__ __forceinline__ float sigm(float x) {
    return __fdividef(1.0f, 1.0f + __expf(-x));
}
__device__ __forceinline__ float tanh_(float x) {
    return 1.0f - __fdividef(2.0f, __expf(2.0f * x) + 1.0f);
}
// 128-thread group barrier (ids 1..4)
__device__ __forceinline__ void gbar(int id) {
    asm volatile("bar.sync %0, 128;" :: "r"(id) : "memory");
}

__global__ void __launch_bounds__(NTHR, 1) gru2_kernel(
    const float* __restrict__ x,
    const float* __restrict__ Wih0, const float* __restrict__ Whh0,
    const float* __restrict__ bih0, const float* __restrict__ bhh0,
    const float* __restrict__ Wih1, const float* __restrict__ Whh1,
    const float* __restrict__ bih1, const float* __restrict__ bhh1,
    const float* __restrict__ Wp,   const float* __restrict__ bp,
    float* __restrict__ out)
{
    extern __shared__ char smraw[];
    Smem* s = reinterpret_cast<Smem*>(smraw);
    const int tid = threadIdx.x;
    const int b0  = blockIdx.x * BT;

    // ---- stage weights k-major; zero h buffers; preload x_0 ----
    for (int idx = tid; idx < Gg * Hh; idx += NTHR) {
        int g = idx >> 6, k = idx & 63;
        s->Wt0 [k][g] = Whh0[idx];
        s->Wt1i[k][g] = Wih1[idx];
        s->Wt1h[k][g] = Whh1[idx];
    }
    for (int idx = tid; idx < 2 * 2 * Hh * PAD_H; idx += NTHR)
        (&s->h0[0][0][0])[idx] = 0.0f;
    if (tid < 2 * BT) (&s->xbuf[0][0][0])[tid] = x[(0 * Bb + b0) * 2 + tid];
    __syncthreads();

    // groups of 128: one warp per SMSP per group; thread = (j, half)
    const int bq    = tid >> 7;        // group 0..3 -> batches [8bq, 8bq+8)
    const int lo    = tid & 127;
    const int half  = lo >> 6;         // k-half / matvec-half
    const int j     = lo & 63;
    const int barid = bq + 1;
    const int bb    = 8 * bq;
    const int po    = 2 * half;        // own p-slots {po, po+1}
    const int ob    = bb + 4 * half;   // own 4-batch base
    const int poX   = 2 - po;          // other half's p base

    // per-thread constants (j-indexed; both halves keep them)
    const float wxr0 = Wih0[2*j],        wxr1 = Wih0[2*j+1];
    const float wxz0 = Wih0[2*(j+64)],   wxz1 = Wih0[2*(j+64)+1];
    const float wxn0 = Wih0[2*(j+128)],  wxn1 = Wih0[2*(j+128)+1];
    const float bxr = bih0[j], bxz = bih0[j+64], bxn = bih0[j+128];
    const float bhr = bhh0[j], bhz = bhh0[j+64], bhn = bhh0[j+128];
    const float cxr = bih1[j], cxz = bih1[j+64], cxn = bih1[j+128];
    const float chr = bhh1[j], chz = bhh1[j+64], chn = bhh1[j+128];

    ull* scrMine = &s->scr[bq][half][j][0];
    const ull* scrOth = &s->scr[bq][half ^ 1][j][0];

    for (int t = 0; t < Tt; t++) {
        const int cur = t & 1, nxt = cur ^ 1;

        float xreg = 0.0f;
        if (half == 0 && j < 16 && t + 1 < Tt)
            xreg = x[((t + 1) * Bb + b0 + bb) * 2 + j];

        // ================= A': layer-0, k-split =================
        {
            ull a[12];   // [g*4+p], g=0:r 1:z 2:n
            if (half == 0) {
                ull pr = dup2(bhr), pz = dup2(bhz), pn = dup2(bhn);
                #pragma unroll
                for (int p = 0; p < 4; p++) { a[p] = pr; a[4+p] = pz; a[8+p] = pn; }
            } else {
                #pragma unroll
                for (int i = 0; i < 12; i++) a[i] = 0ull;
            }
            const int k0 = 32 * half;
            #pragma unroll 8
            for (int kk = 0; kk < 32; kk++) {
                int k = k0 + kk;
                ull wr = dup2(s->Wt0[k][j]);
                ull wz = dup2(s->Wt0[k][j + 64]);
                ull wn = dup2(s->Wt0[k][j + 128]);
                ulonglong2 ha = *(const ulonglong2*)&s->h0[cur][k][bb];
                ulonglong2 hb = *(const ulonglong2*)&s->h0[cur][k][bb + 4];
                fma2(a[0], wr, ha.x); fma2(a[1], wr, ha.y);
                fma2(a[2], wr, hb.x); fma2(a[3], wr, hb.y);
                fma2(a[4], wz, ha.x); fma2(a[5], wz, ha.y);
                fma2(a[6], wz, hb.x); fma2(a[7], wz, hb.y);
                fma2(a[8], wn, ha.x); fma2(a[9], wn, ha.y);
                fma2(a[10], wn, hb.x); fma2(a[11], wn, hb.y);
            }
            // send partials for the other half's batches
            scrMine[0] = a[poX];     scrMine[1] = a[poX + 1];
            scrMine[2] = a[4 + poX]; scrMine[3] = a[5 + poX];
            scrMine[4] = a[8 + poX]; scrMine[5] = a[9 + poX];
            gbar(barid);
            ull sR0 = fadd2(a[po],     scrOth[0]);
            ull sR1 = fadd2(a[po + 1], scrOth[1]);
            ull sZ0 = fadd2(a[4 + po], scrOth[2]);
            ull sZ1 = fadd2(a[5 + po], scrOth[3]);
            ull sN0 = fadd2(a[8 + po], scrOth[4]);
            ull sN1 = fadd2(a[9 + po], scrOth[5]);
            // gate tail for own 4 batches
            ulonglong2 hov = *(const ulonglong2*)&s->h0[cur][j][ob];
            ull sRa[2] = { sR0, sR1 }, sZa[2] = { sZ0, sZ1 }, sNa[2] = { sN0, sN1 };
            ull hoa[2] = { hov.x, hov.y };
            float hnew[4];
            #pragma unroll
            for (int q = 0; q < 2; q++) {
                float4 xq = *(const float4*)&s->xbuf[cur][ob + 2 * q][0];
                float sr0, sr1, sz0, sz1, sn0, sn1, ho0, ho1;
                upk2(sRa[q], sr0, sr1); upk2(sZa[q], sz0, sz1);
                upk2(sNa[q], sn0, sn1); upk2(hoa[q], ho0, ho1);
                float xr0 = fmaf(wxr0, xq.x, fmaf(wxr1, xq.y, bxr));
                float xz0 = fmaf(wxz0, xq.x, fmaf(wxz1, xq.y, bxz));
                float xn0 = fmaf(wxn0, xq.x, fmaf(wxn1, xq.y, bxn));
                float xr1 = fmaf(wxr0, xq.z, fmaf(wxr1, xq.w, bxr));
                float xz1 = fmaf(wxz0, xq.z, fmaf(wxz1, xq.w, bxz));
                float xn1 = fmaf(wxn0, xq.z, fmaf(wxn1, xq.w, bxn));
                float r0 = sigm(xr0 + sr0), z0 = sigm(xz0 + sz0);
                float n0 = tanh_(fmaf(r0, sn0, xn0));
                float r1 = sigm(xr1 + sr1), z1 = sigm(xz1 + sz1);
                float n1 = tanh_(fmaf(r1, sn1, xn1));
                hnew[2*q]     = n0 + z0 * (ho0 - n0);
                hnew[2*q + 1] = n1 + z1 * (ho1 - n1);
            }
            *(float4*)&s->h0[nxt][j][ob] = make_float4(hnew[0], hnew[1], hnew[2], hnew[3]);
        }
        if (half == 0 && j < 16 && t + 1 < Tt)
            (&s->xbuf[nxt][bb][0])[j] = xreg;
        gbar(barid);   // h0[nxt] complete -> C' may read all rows

        // ===== C': layer-1, matvec-split (half0: x-side, half1: h-side) =====
        {
            ull m[12];
            if (half == 0) {
                ull p1 = dup2(cxr), p2 = dup2(cxz), p3 = dup2(cxn);
                #pragma unroll
                for (int p = 0; p < 4; p++) { m[p] = p1; m[4+p] = p2; m[8+p] = p3; }
                #pragma unroll 4
                for (int k = 0; k < Hh; k++) {
                    ull wr = dup2(s->Wt1i[k][j]);
                    ull wz = dup2(s->Wt1i[k][j + 64]);
                    ull wn = dup2(s->Wt1i[k][j + 128]);
                    ulonglong2 ha = *(const ulonglong2*)&s->h0[nxt][k][bb];
                    ulonglong2 hb = *(const ulonglong2*)&s->h0[nxt][k][bb + 4];
                    fma2(m[0], wr, ha.x); fma2(m[1], wr, ha.y);
                    fma2(m[2], wr, hb.x); fma2(m[3], wr, hb.y);
                    fma2(m[4], wz, ha.x); fma2(m[5], wz, ha.y);
                    fma2(m[6], wz, hb.x); fma2(m[7], wz, hb.y);
                    fma2(m[8], wn, ha.x); fma2(m[9], wn, ha.y);
                    fma2(m[10], wn, hb.x); fma2(m[11], wn, hb.y);
                }
            } else {
                ull p1 = dup2(chr), p2 = dup2(chz), p3 = dup2(chn);
                #pragma unroll
                for (int p = 0; p < 4; p++) { m[p] = p1; m[4+p] = p2; m[8+p] = p3; }
                #pragma unroll 4
                for (int k = 0; k < Hh; k++) {
                    ull wr = dup2(s->Wt1h[k][j]);
                    ull wz = dup2(s->Wt1h[k][j + 64]);
                    ull wn = dup2(s->Wt1h[k][j + 128]);
                    ulonglong2 ha = *(const ulonglong2*)&s->h1[cur][k][bb];
                    ulonglong2 hb = *(const ulonglong2*)&s->h1[cur][k][bb + 4];
                    fma2(m[0], wr, ha.x); fma2(m[1], wr, ha.y);
                    fma2(m[2], wr, hb.x); fma2(m[3], wr, hb.y);
                    fma2(m[4], wz, ha.x); fma2(m[5], wz, ha.y);
                    fma2(m[6], wz, hb.x); fma2(m[7], wz, hb.y);
                    fma2(m[8], wn, ha.x); fma2(m[9], wn, ha.y);
                    fma2(m[10], wn, hb.x); fma2(m[11], wn, hb.y);
                }
            }
            // send own matvec's partials for the other half's batches
            scrMine[0] = m[poX];     scrMine[1] = m[poX + 1];
            scrMine[2] = m[4 + poX]; scrMine[3] = m[5 + poX];
            scrMine[4] = m[8 + poX]; scrMine[5] = m[9 + poX];
            gbar(barid);
            // own batches: x-side and h-side (one from regs, one from scratch)
            ull xr_[2], xz_[2], xn_[2], hr_[2], hz_[2], hn_[2];
            if (half == 0) {
                xr_[0] = m[po]; xr_[1] = m[po+1];
                xz_[0] = m[4+po]; xz_[1] = m[5+po];
                xn_[0] = m[8+po]; xn_[1] = m[9+po];
                hr_[0] = scrOth[0]; hr_[1] = scrOth[1];
                hz_[0] = scrOth[2]; hz_[1] = scrOth[3];
                hn_[0] = scrOth[4]; hn_[1] = scrOth[5];
            } else {
                hr_[0] = m[po]; hr_[1] = m[po+1];
                hz_[0] = m[4+po]; hz_[1] = m[5+po];
                hn_[0] = m[8+po]; hn_[1] = m[9+po];
                xr_[0] = scrOth[0]; xr_[1] = scrOth[1];
                xz_[0] = scrOth[2]; xz_[1] = scrOth[3];
                xn_[0] = scrOth[4]; xn_[1] = scrOth[5];
            }
            ulonglong2 hov = *(const ulonglong2*)&s->h1[cur][j][ob];
            ull hoa[2] = { hov.x, hov.y };
            float hnew[4];
            #pragma unroll
            for (int q = 0; q < 2; q++) {
                float a0, a1, b0f, b1f, c0, c1, d0, d1, e0, e1, f0, f1, ho0, ho1;
                upk2(xr_[q], a0, a1); upk2(hr_[q], b0f, b1f);
                upk2(xz_[q], c0, c1); upk2(hz_[q], d0, d1);
                upk2(xn_[q], e0, e1); upk2(hn_[q], f0, f1);
                upk2(hoa[q], ho0, ho1);
                float r0 = sigm(a0 + b0f), z0 = sigm(c0 + d0);
                float n0 = tanh_(fmaf(r0, f0, e0));
                float r1 = sigm(a1 + b1f), z1 = sigm(c1 + d1);
                float n1 = tanh_(fmaf(r1, f1, e1));
                hnew[2*q]     = n0 + z0 * (ho0 - n0);
                hnew[2*q + 1] = n1 + z1 * (ho1 - n1);
            }
            *(float4*)&s->h1[nxt][j][ob] = make_float4(hnew[0], hnew[1], hnew[2], hnew[3]);
        }
        gbar(barid);
    }

    __syncthreads();

    // ---- final projection: final states in buffer 0 (Tt even) ----
    if (tid < BT) {
        float acc = bp[0];
        #pragma unroll 8
        for (int k = 0; k < Hh; k++) acc = fmaf(Wp[k],      s->h0[0][k][tid], acc);
        #pragma unroll 8
        for (int k = 0; k < Hh; k++) acc = fmaf(Wp[64 + k], s->h1[0][k][tid], acc);
        out[b0 + tid] = acc;
    }
}

extern "C" void kernel_launch(void* const* d_in, const int* in_sizes, int n_in,
                              void* d_out, int out_size)
{
    const float* x    = (const float*)d_in[0];
    const float* Wih0 = (const float*)d_in[1];
    const float* Whh0 = (const float*)d_in[2];
    const float* bih0 = (const float*)d_in[3];
    const float* bhh0 = (const float*)d_in[4];
    const float* Wih1 = (const float*)d_in[5];
    const float* Whh1 = (const float*)d_in[6];
    const float* bih1 = (const float*)d_in[7];
    const float* bhh1 = (const float*)d_in[8];
    const float* Wp   = (const float*)d_in[9];
    const float* bp   = (const float*)d_in[10];
    float* out = (float*)d_out;

    cudaFuncSetAttribute(gru2_kernel,
                         cudaFuncAttributeMaxDynamicSharedMemorySize,
                         (int)sizeof(Smem));
    gru2_kernel<<<NCTA, NTHR, sizeof(Smem)>>>(
        x, Wih0, Whh0, bih0, bhh0, Wih1, Whh1, bih1, bhh1, Wp, bp, out);
}